// round 7
// baseline (speedup 1.0000x reference)
#include <cuda_runtime.h>
#include <math_constants.h>

#define NPTS 256
#define NT 32       // one warp per batch
#define NC 8        // columns (and rows) owned per lane
#define NBATCH 8
#define FULLMASK 0xffffffffu

// Per-batch matched-cost sums (no device allocation allowed).
__device__ float g_batch_sum[NBATCH];

// Order-preserving float <-> uint maps (REDUX.MIN on float keys).
__device__ __forceinline__ unsigned ford(float f) {
    unsigned u = __float_as_uint(f);
    return (u & 0x80000000u) ? ~u : (u | 0x80000000u);
}
__device__ __forceinline__ float funord(unsigned x) {
    unsigned u = (x & 0x80000000u) ? (x & 0x7fffffffu) : ~x;
    return __uint_as_float(u);
}
// Single-MUFU sqrt for the search phases (final loss uses IEEE sqrtf).
__device__ __forceinline__ float fsqrt_fast(float x) {
    float r;
    asm("sqrt.approx.f32 %0, %1;" : "=f"(r) : "f"(x));
    return r;
}

// One CTA = one warp = one batch. JV: column reduction + greedy init, then
// warp-synchronous shortest augmenting paths (no __syncthreads anywhere in
// the search loop). Lane l owns cols {l, l+32, ..., l+224} and same rows.
__global__ __launch_bounds__(NT) void emd_lsa_kernel(
    const float* __restrict__ pred, const float* __restrict__ label) {
    const int b = blockIdx.x;
    const int lane = threadIdx.x;

    __shared__ float px[NPTS], py[NPTS], pz[NPTS];
    __shared__ float sx[NPTS], sy[NPTS], sz[NPTS];
    __shared__ float u_s[NPTS], shortest_s[NPTS];
    __shared__ int row4col_s[NPTS], col4row_s[NPTS], path_s[NPTS];
    __shared__ int rowclaim[NPTS];

    // ---- load coords + init state ----
    const float* P = pred + (size_t)b * NPTS * 3;
    const float* L = label + (size_t)b * NPTS * 3;
#pragma unroll
    for (int k = 0; k < NC; ++k) {
        int j = lane + NT * k;
        px[j] = P[j * 3 + 0];
        py[j] = P[j * 3 + 1];
        pz[j] = P[j * 3 + 2];
        sx[j] = L[j * 3 + 0];
        sy[j] = L[j * 3 + 1];
        sz[j] = L[j * 3 + 2];
        row4col_s[j] = -1;
        col4row_s[j] = -1;
        u_s[j] = 0.0f;
        rowclaim[j] = 0x7fffffff;
    }
    __syncwarp();

    // own-column label coords + duals in registers
    float lx[NC], ly[NC], lz[NC], v[NC];
#pragma unroll
    for (int k = 0; k < NC; ++k) {
        int j = lane + NT * k;
        lx[k] = sx[j];
        ly[k] = sy[j];
        lz[k] = sz[j];
    }

    // ---- phase 1: column reduction v[j]=min_i c(i,j) + greedy claim ----
#pragma unroll
    for (int k = 0; k < NC; ++k) {
        float vmin = CUDART_INF_F;
        int varg = 0;
        for (int i = 0; i < NPTS; ++i) {
            float dx = px[i] - lx[k], dy = py[i] - ly[k], dz = pz[i] - lz[k];
            float c = fsqrt_fast(fmaf(dx, dx, fmaf(dy, dy, dz * dz)));
            if (c < vmin) { vmin = c; varg = i; }
        }
        v[k] = vmin;
        atomicMin(&rowclaim[varg], lane + NT * k);  // min-col claim: deterministic
    }
    __syncwarp();
#pragma unroll
    for (int k = 0; k < NC; ++k) {
        int r = lane + NT * k;
        int c = rowclaim[r];
        if (c != 0x7fffffff) { col4row_s[r] = c; row4col_s[c] = r; }
    }
    __syncwarp();

    // ---- phase 2: shortest augmenting paths for free rows ----
    for (int cur = 0; cur < NPTS; ++cur) {
        if (col4row_s[cur] >= 0) continue;  // uniform read, warp-coherent

        float shortest[NC];
        int path[NC];
#pragma unroll
        for (int k = 0; k < NC; ++k) {
            shortest[k] = CUDART_INF_F;
            path[k] = 0;
        }
        unsigned SCm = 0;  // bitmask over this lane's 8 columns
        unsigned SRm = (lane == (cur & 31)) ? (1u << (cur >> 5)) : 0u;
        int i = cur;
        float mv = 0.0f;
        int sink;

        while (true) {
            const float ui = u_s[i];
            const float pix = px[i], piy = py[i], piz = pz[i];
            unsigned lkey = 0xffffffffu;
#pragma unroll
            for (int k = 0; k < NC; ++k) {
                const unsigned col = (unsigned)(lane + NT * k);
                unsigned key;
                if (!((SCm >> k) & 1u)) {
                    float dx = pix - lx[k], dy = piy - ly[k], dz = piz - lz[k];
                    float c = fsqrt_fast(fmaf(dx, dx, fmaf(dy, dy, dz * dz)));
                    float r = mv + c - ui - v[k];
                    if (r < shortest[k]) { shortest[k] = r; path[k] = i; }
                    key = (ford(shortest[k]) & 0xffffff00u) | col;
                } else {
                    key = 0xffffff00u | col;  // scanned: worse than any live key
                }
                lkey = min(lkey, key);
            }
            // warp argmin: packed key returns (value, column) to every lane
            unsigned best = __reduce_min_sync(FULLMASK, lkey);
            const int bj = (int)(best & 0xffu);
            mv = funord(best & 0xffffff00u);  // truncated min (see theory note)
            if (lane == (bj & 31)) SCm |= 1u << (bj >> 5);

            const int r4 = row4col_s[bj];
            if (r4 < 0) { sink = bj; break; }
            i = r4;
            if (lane == (i & 31)) SRm |= 1u << (i >> 5);
        }

        // publish search results once (duals + augment need arbitrary index)
#pragma unroll
        for (int k = 0; k < NC; ++k) {
            int j = lane + NT * k;
            shortest_s[j] = shortest[k];
            path_s[j] = path[k];
        }
        __syncwarp();

        // dual updates (read OLD col4row, before augment)
#pragma unroll
        for (int k = 0; k < NC; ++k) {
            int r = lane + NT * k;
            if ((SRm >> k) & 1u) {
                if (r == cur) u_s[r] += mv;
                else u_s[r] += mv - shortest_s[col4row_s[r]];
            }
            if ((SCm >> k) & 1u) v[k] -= mv - shortest[k];
        }
        __syncwarp();

        // augment along alternating path (short serial walk on lane 0)
        if (lane == 0) {
            int j = sink;
            while (true) {
                int ii = path_s[j];
                row4col_s[j] = ii;
                int nj = col4row_s[ii];
                col4row_s[ii] = j;
                j = nj;
                if (ii == cur) break;
            }
        }
        __syncwarp();
    }

    // ---- matched distance per row, exact IEEE recompute + warp-tree sum ----
    float acc = 0.0f;
#pragma unroll
    for (int k = 0; k < NC; ++k) {
        int r = lane + NT * k;
        int j = col4row_s[r];
        float dx = px[r] - sx[j];
        float dy = py[r] - sy[j];
        float dz = pz[r] - sz[j];
        acc += sqrtf(fmaf(dx, dx, fmaf(dy, dy, dz * dz)));
    }
#pragma unroll
    for (int off = 16; off > 0; off >>= 1)
        acc += __shfl_down_sync(FULLMASK, acc, off);
    if (lane == 0) g_batch_sum[b] = acc;
}

// Deterministic fixed-order final reduction.
__global__ void emd_reduce_kernel(float* __restrict__ out) {
    float s = 0.0f;
#pragma unroll
    for (int bb = 0; bb < NBATCH; ++bb) s += g_batch_sum[bb];
    out[0] = s / (float)(NBATCH * NPTS);
}

extern "C" void kernel_launch(void* const* d_in, const int* in_sizes, int n_in,
                              void* d_out, int out_size) {
    const float* pred = (const float*)d_in[0];
    const float* label = (const float*)d_in[1];
    float* out = (float*)d_out;
    emd_lsa_kernel<<<NBATCH, NT>>>(pred, label);
    emd_reduce_kernel<<<1, 1>>>(out);
}

// round 8
// speedup vs baseline: 2.1584x; 2.1584x over previous
#include <cuda_runtime.h>
#include <math_constants.h>

#define NPTS 256
#define NT 128      // threads per CTA (4 warps: spreads relax issue over SMSPs)
#define NC 2        // columns (and rows) owned per thread
#define NBATCH 8
#define FULLMASK 0xffffffffu

// Per-batch matched-cost sums (no device allocation allowed).
__device__ float g_batch_sum[NBATCH];

// Order-preserving float <-> uint maps (REDUX.MIN on float keys).
__device__ __forceinline__ unsigned ford(float f) {
    unsigned u = __float_as_uint(f);
    return (u & 0x80000000u) ? ~u : (u | 0x80000000u);
}
__device__ __forceinline__ float funord(unsigned x) {
    unsigned u = (x & 0x80000000u) ? (x & 0x7fffffffu) : ~x;
    return __uint_as_float(u);
}
// Single-MUFU sqrt for the search phases (final loss uses IEEE sqrtf).
__device__ __forceinline__ float fsqrt_fast(float x) {
    float r;
    asm("sqrt.approx.f32 %0, %1;" : "=f"(r) : "f"(x));
    return r;
}

// One CTA per batch. JV: column reduction + greedy, row reduction + second
// greedy, then shortest augmenting paths. Thread t owns cols {t, t+128} and
// rows {t, t+128}.
__global__ __launch_bounds__(NT) void emd_lsa_kernel(
    const float* __restrict__ pred, const float* __restrict__ label) {
    const int b = blockIdx.x;
    const int tid = threadIdx.x;
    const int warp = tid >> 5;

    __shared__ float px[NPTS], py[NPTS], pz[NPTS];
    __shared__ float sx[NPTS], sy[NPTS], sz[NPTS];
    __shared__ float u_s[NPTS], v_s[NPTS], shortest_s[NPTS];
    __shared__ int row4col_s[NPTS], col4row_s[NPTS], path_s[NPTS];
    __shared__ int claim[NPTS];
    __shared__ __align__(16) unsigned wslot[2][4];  // double-buffered warp keys

    // ---- load coords + init state ----
    const float* P = pred + (size_t)b * NPTS * 3;
    const float* L = label + (size_t)b * NPTS * 3;
#pragma unroll
    for (int k = 0; k < NC; ++k) {
        int j = tid + NT * k;
        px[j] = P[j * 3 + 0];
        py[j] = P[j * 3 + 1];
        pz[j] = P[j * 3 + 2];
        sx[j] = L[j * 3 + 0];
        sy[j] = L[j * 3 + 1];
        sz[j] = L[j * 3 + 2];
        row4col_s[j] = -1;
        col4row_s[j] = -1;
        u_s[j] = 0.0f;
        claim[j] = 0x7fffffff;
    }
    __syncthreads();

    // own-column label coords in registers
    float lx[NC], ly[NC], lz[NC], v[NC];
#pragma unroll
    for (int k = 0; k < NC; ++k) {
        int j = tid + NT * k;
        lx[k] = sx[j];
        ly[k] = sy[j];
        lz[k] = sz[j];
    }

    // ---- phase 1: column reduction v[j]=min_i c(i,j) + greedy row claim ----
#pragma unroll
    for (int k = 0; k < NC; ++k) {
        float vmin = CUDART_INF_F;
        int varg = 0;
        for (int i = 0; i < NPTS; ++i) {
            float dx = px[i] - lx[k], dy = py[i] - ly[k], dz = pz[i] - lz[k];
            float c = fsqrt_fast(fmaf(dx, dx, fmaf(dy, dy, dz * dz)));
            if (c < vmin) { vmin = c; varg = i; }
        }
        v[k] = vmin;
        v_s[tid + NT * k] = vmin;  // publish for phase 1b
        atomicMin(&claim[varg], tid + NT * k);  // deterministic min-col claim
    }
    __syncthreads();
#pragma unroll
    for (int k = 0; k < NC; ++k) {
        int r = tid + NT * k;
        int c = claim[r];  // claim indexed by row here
        if (c != 0x7fffffff) { col4row_s[r] = c; row4col_s[c] = r; }
        claim[r] = 0x7fffffff;  // reset for phase 1b (column claims)
    }
    __syncthreads();

    // ---- phase 1b: row reduction u[i]=min_j (c-v) + second greedy ----
    // Dual-feasible by construction; assigned pairs have zero reduced cost,
    // so complementary slackness holds and SAP stays exactly optimal.
#pragma unroll
    for (int k = 0; k < NC; ++k) {
        int r = tid + NT * k;
        if (col4row_s[r] < 0) {
            const float prx = px[r], pry = py[r], prz = pz[r];
            float umin = CUDART_INF_F;
            int uarg = 0;
            for (int j = 0; j < NPTS; ++j) {
                float dx = prx - sx[j], dy = pry - sy[j], dz = prz - sz[j];
                float c = fsqrt_fast(fmaf(dx, dx, fmaf(dy, dy, dz * dz)));
                float s = c - v_s[j];
                if (s < umin) { umin = s; uarg = j; }
            }
            u_s[r] = umin;
            if (row4col_s[uarg] < 0) atomicMin(&claim[uarg], r);
        }
    }
    __syncthreads();
#pragma unroll
    for (int k = 0; k < NC; ++k) {
        int j = tid + NT * k;
        int r = claim[j];  // claim indexed by column here
        if (r != 0x7fffffff) { row4col_s[j] = r; col4row_s[r] = j; }
    }
    __syncthreads();

    // ---- phase 2: shortest augmenting paths for remaining free rows ----
    for (int cur = 0; cur < NPTS; ++cur) {
        if (col4row_s[cur] >= 0) continue;  // uniform smem read

        float shortest[NC];
        int path[NC];
        bool SC[NC], SR[NC];
#pragma unroll
        for (int k = 0; k < NC; ++k) {
            shortest[k] = CUDART_INF_F;
            path[k] = 0;
            SC[k] = false;
            SR[k] = ((tid + NT * k) == cur);
        }
        int i = cur;
        float mv = 0.0f;
        int parity = 0;
        int sink = -1;

        while (true) {
            const float ui = u_s[i];
            const float pix = px[i], piy = py[i], piz = pz[i];
            unsigned lkey = 0xffffffffu;
#pragma unroll
            for (int k = 0; k < NC; ++k) {
                const unsigned col = (unsigned)(tid + NT * k);
                unsigned key;
                if (!SC[k]) {
                    float dx = pix - lx[k], dy = piy - ly[k], dz = piz - lz[k];
                    float c = fsqrt_fast(fmaf(dx, dx, fmaf(dy, dy, dz * dz)));
                    float r = mv + c - ui - v[k];
                    if (r < shortest[k]) { shortest[k] = r; path[k] = i; }
                    key = (ford(shortest[k]) & 0xffffff00u) | col;
                } else {
                    key = 0xffffff00u | col;  // scanned: behind any live key
                }
                lkey = min(lkey, key);
            }
            // warp min; unique low bits -> single writer per warp
            unsigned m = __reduce_min_sync(FULLMASK, lkey);
            if (lkey == m) wslot[parity][warp] = m;
            __syncthreads();

            uint4 ws = *(const uint4*)&wslot[parity][0];
            unsigned best = min(min(ws.x, ws.y), min(ws.z, ws.w));
            parity ^= 1;

            const int bj = (int)(best & 0xffu);
            mv = funord(best & 0xffffff00u);  // truncated min: no STS/LDS round trip
            const int r4 = row4col_s[bj];
            if (tid == (bj & (NT - 1))) SC[bj >> 7] = true;
            if (r4 < 0) { sink = bj; break; }
            i = r4;
            if (tid == (i & (NT - 1))) SR[i >> 7] = true;
        }

        // publish search results once (duals + augment need arbitrary index)
#pragma unroll
        for (int k = 0; k < NC; ++k) {
            int j = tid + NT * k;
            shortest_s[j] = shortest[k];
            path_s[j] = path[k];
        }
        __syncthreads();

        // dual updates (read OLD col4row, before augment)
#pragma unroll
        for (int k = 0; k < NC; ++k) {
            int r = tid + NT * k;
            if (SR[k]) {
                if (r == cur) u_s[r] += mv;
                else u_s[r] += mv - shortest_s[col4row_s[r]];
            }
            if (SC[k]) v[k] -= mv - shortest[k];
        }
        __syncthreads();

        // augment along alternating path (short serial walk)
        if (tid == 0) {
            int j = sink;
            while (true) {
                int ii = path_s[j];
                row4col_s[j] = ii;
                int nj = col4row_s[ii];
                col4row_s[ii] = j;
                j = nj;
                if (ii == cur) break;
            }
        }
        __syncthreads();
    }

    // ---- matched distance per row, exact IEEE recompute ----
#pragma unroll
    for (int k = 0; k < NC; ++k) {
        int r = tid + NT * k;
        int j = col4row_s[r];
        float dx = px[r] - sx[j];
        float dy = py[r] - sy[j];
        float dz = pz[r] - sz[j];
        shortest_s[r] = sqrtf(fmaf(dx, dx, fmaf(dy, dy, dz * dz)));
    }
    __syncthreads();
#pragma unroll
    for (int s = 128; s > 0; s >>= 1) {
        if (tid < s) shortest_s[tid] += shortest_s[tid + s];
        __syncthreads();
    }
    if (tid == 0) g_batch_sum[b] = shortest_s[0];
}

// Deterministic fixed-order final reduction.
__global__ void emd_reduce_kernel(float* __restrict__ out) {
    float s = 0.0f;
#pragma unroll
    for (int bb = 0; bb < NBATCH; ++bb) s += g_batch_sum[bb];
    out[0] = s / (float)(NBATCH * NPTS);
}

extern "C" void kernel_launch(void* const* d_in, const int* in_sizes, int n_in,
                              void* d_out, int out_size) {
    const float* pred = (const float*)d_in[0];
    const float* label = (const float*)d_in[1];
    float* out = (float*)d_out;
    emd_lsa_kernel<<<NBATCH, NT>>>(pred, label);
    emd_reduce_kernel<<<1, 1>>>(out);
}